// round 5
// baseline (speedup 1.0000x reference)
#include <cuda_runtime.h>
#include <cstdint>
#include <cstddef>

#define S_LEN 512
#define HSTRIDE 132
#define XSTRIDE 68

// g_W float offsets.
// 64-k quarter layout (seq mats):  addr = i*2048 + j*16 + q*4 + e, k = q*16+i*4+e, i<4
// 128-k quarter layout (h/x mats): addr = i*2048 + j*16 + q*4 + e, k = q*32+i*4+e, i<8
// ctx mats keep k-quad:            addr = kq*512 + j*4 + e,        k = kq*4+e, kq<8
#define OFF_WIN0S 0
#define OFF_WG0S  8192
#define OFF_WG0H  16384
#define OFF_WREC0 32768
#define OFF_WIN1  49152
#define OFF_WG1X  65536
#define OFF_WG1H  81920
#define OFF_WREC1 98304
#define OFF_WIN0C 114688
#define OFF_WG0C  118784
#define W_TOTAL   122880

__device__ __align__(16) float g_W[W_TOTAL];

// ---------------- packed fp32x2 helpers (SASS FFMA2, PTX-only) ----------------
__device__ __forceinline__ unsigned long long ffma2(unsigned long long a,
                                                    unsigned long long b,
                                                    unsigned long long c) {
    unsigned long long d;
    asm("fma.rn.f32x2 %0, %1, %2, %3;" : "=l"(d) : "l"(a), "l"(b), "l"(c));
    return d;
}
__device__ __forceinline__ float redu2(unsigned long long v) {
    float lo, hi;
    asm("mov.b64 {%0, %1}, %2;" : "=f"(lo), "=f"(hi) : "l"(v));
    return lo + hi;
}
__device__ __forceinline__ float sigm(float x) {
    return __fdividef(1.0f, 1.0f + __expf(-x));
}
__device__ __forceinline__ float fast_tanh(float x) {
    float ax = fabsf(x);
    float e = __expf(ax + ax);
    float t = 1.0f - __fdividef(2.0f, e + 1.0f);
    return copysignf(t, x);
}
// reduce packed acc + combine 4 k-quarters (lane bits 3,4)
__device__ __forceinline__ float redq(unsigned long long v) {
    float r = redu2(v);
    r += __shfl_xor_sync(0xffffffffu, r, 8);
    r += __shfl_xor_sync(0xffffffffu, r, 16);
    return r;
}
// branchless pick of own batch q from the 4 reduced sums
__device__ __forceinline__ float sel4(const float r[4], int q) {
    float t0 = (q & 1) ? r[1] : r[0];
    float t1 = (q & 1) ? r[3] : r[2];
    return (q & 2) ? t1 : t0;
}

// ---------------- weight layout prep ----------------
__global__ void __launch_bounds__(256) prep_weights(
    const float* __restrict__ Win0, const float* __restrict__ Wg0,
    const float* __restrict__ Wrec0, const float* __restrict__ Win1,
    const float* __restrict__ Wrec1, const float* __restrict__ Wg1) {
    int idx = blockIdx.x * 256 + threadIdx.x;
    if (idx >= W_TOTAL) return;
    float v;
    if (idx < 16384) {  // 64-k quarter layout: Win0 seq / Wg0 seq
        int m = idx >> 13;
        int a = idx & 8191;
        int i = a >> 11, j = (a >> 4) & 127, qq = (a >> 2) & 3, e = a & 3;
        int k = qq * 16 + i * 4 + e;
        v = m ? Wg0[j * 224 + k] : Win0[j * 96 + k];
    } else if (idx < 114688) {  // 128-k quarter layout
        int m = (idx - 16384) >> 14;
        int a = (idx - 16384) & 16383;
        int i = a >> 11, j = (a >> 4) & 127, qq = (a >> 2) & 3, e = a & 3;
        int k = qq * 32 + i * 4 + e;
        switch (m) {
            case 0: v = Wg0[j * 224 + 96 + k]; break;
            case 1: v = Wrec0[j * 128 + k]; break;
            case 2: v = Win1[j * 128 + k]; break;
            case 3: v = Wg1[j * 256 + k]; break;
            case 4: v = Wg1[j * 256 + 128 + k]; break;
            default: v = Wrec1[j * 128 + k]; break;
        }
    } else {  // ctx parts, k-quad layout
        int m = (idx - 114688) >> 12;
        int a = (idx - 114688) & 4095;
        int j = (a >> 2) & 127;
        int k = ((a >> 9) << 2) | (a & 3);
        v = m ? Wg0[j * 224 + 64 + k] : Win0[j * 96 + 64 + k];
    }
    g_W[idx] = v;
}

// Quarter-split dual mat-vec. Thread covers row jl, k-quarter q (folded into the
// W pointers and the x pointer). ITERS = (k/4)/4. Results reduced across
// quarters via shfl so every lane gets the full dots for its row, batches 0..3.
template <int ITERS, int XS>
__device__ __forceinline__ void dualmv_q(const float* __restrict__ Wa,
                                         const float* __restrict__ Wb,
                                         const float* __restrict__ xq,
                                         float ra[4], float rb[4]) {
    unsigned long long a[4] = {0, 0, 0, 0};
    unsigned long long c[4] = {0, 0, 0, 0};
#pragma unroll
    for (int i = 0; i < ITERS; ++i) {
        ulonglong2 wa = __ldg(reinterpret_cast<const ulonglong2*>(Wa + (size_t)i * 2048));
        ulonglong2 wb = __ldg(reinterpret_cast<const ulonglong2*>(Wb + (size_t)i * 2048));
#pragma unroll
        for (int b = 0; b < 4; ++b) {
            ulonglong2 xv = *reinterpret_cast<const ulonglong2*>(xq + b * XS + i * 16);
            a[b] = ffma2(wa.x, xv.x, a[b]);
            a[b] = ffma2(wa.y, xv.y, a[b]);
            c[b] = ffma2(wb.x, xv.x, c[b]);
            c[b] = ffma2(wb.y, xv.y, c[b]);
        }
    }
#pragma unroll
    for (int b = 0; b < 4; ++b) {
        ra[b] = redq(a[b]);
        rb[b] = redq(c[b]);
    }
}

// RK4 for one cell, per-lane (row, batch=q) ownership. hb: own pair's h at cell
// entry (updated to the new h on exit). In the last sub-phase, WRITE_H0 writes
// h0v (cell-0 state) into nx instead of the new h.
template <bool WRITE_H0>
__device__ __forceinline__ void rk4_cell(const float* __restrict__ Wg,
                                         const float* __restrict__ Wr, float itau,
                                         float xin, float xg, float& hb, float h0v,
                                         float*& cu, float*& nx, int wslot, int qoff,
                                         int q) {
    float ka = 0.f;
    float ht = hb;
    const float h0 = hb;
#pragma unroll
    for (int sub = 0; sub < 4; ++sub) {
        float ra[4], rb[4];
        dualmv_q<8, HSTRIDE>(Wg, Wr, cu + qoff, ra, rb);
        const float kw = (sub == 0 || sub == 3) ? 1.0f : 2.0f;
        const float cv = (sub < 2) ? 0.5f : 1.0f;
        float gate = sigm(fast_tanh(sel4(ra, q) + xg));
        float kv = fmaf(gate, sel4(rb, q), fmaf(-ht, itau, xin));
        ka = fmaf(kw, kv, ka);
        float nh = (sub < 3) ? fmaf(cv, kv, h0)
                             : fast_tanh(fmaf(ka, 0.16666667f, h0));
        ht = nh;
        nx[wslot] = (sub == 3 && WRITE_H0) ? h0v : nh;
        __syncthreads();
        float* t = cu; cu = nx; nx = t;
    }
    hb = ht;
}

// ---------------- persistent recurrence: 128 CTAs x 512 threads ----------------
// Warp w covers rows jl = w*8 + (lane&7); quarter q = lane>>3 covers one k-quarter
// in the matmuls and owns batch q in the elementwise RK4 update.
__global__ void __launch_bounds__(512, 1)
ltc_recurrent(const float* __restrict__ seq, const float* __restrict__ ctx,
              const float* __restrict__ tau0, const float* __restrict__ bg0,
              const float* __restrict__ tau1, const float* __restrict__ bg1,
              const float* __restrict__ W1, const float* __restrict__ b1,
              const float* __restrict__ W2, const float* __restrict__ b2,
              float* __restrict__ out) {
    __shared__ __align__(16) float hhA[4 * HSTRIDE];
    __shared__ __align__(16) float hhB[4 * HSTRIDE];
    __shared__ __align__(16) float xs[4 * XSTRIDE];
    __shared__ __align__(16) float xc[4 * 32];
    __shared__ __align__(16) float st0[512];
    __shared__ __align__(16) float st1[512];
    const int tid = threadIdx.x;
    const int lane = tid & 31;
    const int w = tid >> 5;
    const int q = lane >> 3;
    const int jl = (w << 3) + (lane & 7);
    const int qoff = q * 4;
    // smem slot of h[jl] in the interleaved quarter layout
    const int hslot = ((jl >> 2) & 7) * 16 + (jl >> 5) * 4 + (jl & 3);
    const int wslot = q * HSTRIDE + hslot;
    const int b0g = blockIdx.x * 4;

    const float it0 = __fdividef(1.0f, log1pf(__expf(tau0[jl])) + 1.0f);
    const float it1 = __fdividef(1.0f, log1pf(__expf(tau1[jl])) + 1.0f);
    const float bg1j = bg1[jl];

    const int wo = jl * 16 + qoff;
    const float* Win0s = g_W + OFF_WIN0S + wo;
    const float* Wg0s  = g_W + OFF_WG0S  + wo;
    const float* Wg0h  = g_W + OFF_WG0H  + wo;
    const float* Wrec0 = g_W + OFF_WREC0 + wo;
    const float* Win1  = g_W + OFF_WIN1  + wo;
    const float* Wg1x  = g_W + OFF_WG1X  + wo;
    const float* Wg1h  = g_W + OFF_WG1H  + wo;
    const float* Wrec1 = g_W + OFF_WREC1 + wo;

    // ---- step-invariant ctx projection (threads 0-127, k-quad layout) ----
    if (tid < 128) {
        int b = tid >> 5, i = tid & 31;
        xc[b * 32 + i] = ctx[(size_t)(b0g + b) * 32 + i];
    }
    __syncthreads();
    if (tid < 128) {
        const int j = tid;
        const float* Wa = g_W + OFF_WIN0C + j * 4;
        const float* Wb = g_W + OFF_WG0C + j * 4;
        unsigned long long a[4] = {0, 0, 0, 0}, c[4] = {0, 0, 0, 0};
#pragma unroll
        for (int kq = 0; kq < 8; ++kq) {
            ulonglong2 wa = __ldg(reinterpret_cast<const ulonglong2*>(Wa + kq * 512));
            ulonglong2 wb = __ldg(reinterpret_cast<const ulonglong2*>(Wb + kq * 512));
#pragma unroll
            for (int b = 0; b < 4; ++b) {
                ulonglong2 xv = *reinterpret_cast<const ulonglong2*>(xc + b * 32 + kq * 4);
                a[b] = ffma2(wa.x, xv.x, a[b]);
                a[b] = ffma2(wa.y, xv.y, a[b]);
                c[b] = ffma2(wb.x, xv.x, c[b]);
                c[b] = ffma2(wb.y, xv.y, c[b]);
            }
        }
        const float bg0j = bg0[j];
#pragma unroll
        for (int b = 0; b < 4; ++b) {
            st0[b * 128 + j] = redu2(a[b]);
            st1[b * 128 + j] = redu2(c[b]) + bg0j;
        }
    }
    __syncthreads();
    const float xinc = st0[q * 128 + jl];
    const float xgc = st1[q * 128 + jl];

    float h0own = 0.f, h1own = 0.f;
    float* cu = hhA;
    float* nx = hhB;
    for (int t = tid; t < 4 * HSTRIDE; t += 512) hhA[t] = 0.f;
    // visibility covered by the bar after the first seq load

    for (int s = 0; s < S_LEN; ++s) {
        // load this step's seq slice into the interleaved quarter layout
        if (tid < 256) {
            int b = tid >> 6, k = tid & 63;
            float v = seq[((size_t)(b0g + b) * S_LEN + s) * 64 + k];
            int sl = ((k >> 2) & 3) * 16 + (k >> 4) * 4 + (k & 3);
            xs[b * XSTRIDE + sl] = v;
        }
        __syncthreads();

        // cell-0 input projections (seq part) + ctx base
        float pa[4], pb[4];
        dualmv_q<4, XSTRIDE>(Win0s, Wg0s, xs + qoff, pa, pb);
        const float xin0 = sel4(pa, q) + xinc;
        const float xg0 = sel4(pb, q) + xgc;

        // cell 0 (cu holds h0; leaves h0_new in cu and h0own)
        rk4_cell<false>(Wg0h, Wrec0, it0, xin0, xg0, h0own, 0.f, cu, nx, wslot,
                        qoff, q);

        // cell-1 input projections from h0_new; stage h1 into nx
        dualmv_q<8, HSTRIDE>(Win1, Wg1x, cu + qoff, pa, pb);
        const float xin1 = sel4(pa, q);
        const float xg1 = sel4(pb, q) + bg1j;
        nx[wslot] = h1own;
        __syncthreads();
        { float* t = cu; cu = nx; nx = t; }

        // cell 1 (last sub writes h0_new back for the next step's cell 0)
        rk4_cell<true>(Wg1h, Wrec1, it1, xin1, xg1, h1own, h0own, cu, nx, wslot,
                       qoff, q);
    }

    // ---- classifier: sigmoid(relu(h1 @ W1^T + b1) @ W2^T + b2) ----
    st0[q * 128 + jl] = h1own;
    __syncthreads();
    if (tid < 128) {
        const int b = tid >> 5, ln = tid & 31;
        float a0 = b1[ln], a1 = b1[ln + 32];
        const float* hv = st0 + b * 128;
        const float* w0 = W1 + ln * 128;
        const float* w1 = W1 + (ln + 32) * 128;
#pragma unroll 8
        for (int k = 0; k < 128; ++k) {
            float h = hv[k];
            a0 = fmaf(h, w0[k], a0);
            a1 = fmaf(h, w1[k], a1);
        }
        a0 = fmaxf(a0, 0.f);
        a1 = fmaxf(a1, 0.f);
        float p = a0 * __ldg(W2 + ln) + a1 * __ldg(W2 + ln + 32);
#pragma unroll
        for (int off = 16; off; off >>= 1) p += __shfl_xor_sync(0xffffffffu, p, off);
        if (ln == 0) out[b0g + b] = sigm(p + b2[0]);
    }
}

extern "C" void kernel_launch(void* const* d_in, const int* in_sizes, int n_in,
                              void* d_out, int out_size) {
    const float* seq   = (const float*)d_in[0];
    const float* ctx   = (const float*)d_in[1];
    const float* tau0  = (const float*)d_in[2];
    const float* Win0  = (const float*)d_in[3];
    const float* Wrec0 = (const float*)d_in[4];
    const float* Wg0   = (const float*)d_in[5];
    const float* bg0   = (const float*)d_in[6];
    const float* tau1  = (const float*)d_in[7];
    const float* Win1  = (const float*)d_in[8];
    const float* Wrec1 = (const float*)d_in[9];
    const float* Wg1   = (const float*)d_in[10];
    const float* bg1   = (const float*)d_in[11];
    const float* W1    = (const float*)d_in[12];
    const float* b1    = (const float*)d_in[13];
    const float* W2    = (const float*)d_in[14];
    const float* b2    = (const float*)d_in[15];
    float* out = (float*)d_out;

    prep_weights<<<(W_TOTAL + 255) / 256, 256>>>(Win0, Wg0, Wrec0, Win1, Wrec1, Wg1);
    ltc_recurrent<<<128, 512>>>(seq, ctx, tau0, bg0, tau1, bg1, W1, b1, W2, b2, out);
}

// round 6
// speedup vs baseline: 1.5846x; 1.5846x over previous
#include <cuda_runtime.h>
#include <cuda_fp16.h>
#include <cstdint>
#include <cstddef>

#define S_LEN 512
#define HSTRIDE 128
#define XSTRIDE 64

// fp16 weight offsets (half elements).
// 64-k mats:  addr = ((i*2+half)*128 + j)*8 + e,  k = half*32 + i*8 + e, i<4
// 128-k mats: addr = ((i*2+half)*128 + j)*8 + e,  k = half*64 + i*8 + e, i<8
#define OFF_WIN0S 0
#define OFF_WG0S  8192
#define OFF_WG0H  16384
#define OFF_WREC0 32768
#define OFF_WIN1  49152
#define OFF_WG1X  65536
#define OFF_WG1H  81920
#define OFF_WREC1 98304
#define WH_TOTAL  114688

__device__ __align__(16) __half g_Wh[WH_TOTAL];
// ctx mats stay fp32, k-quad layout: addr = kq*512 + j*4 + e, k = kq*4+e, kq<8
__device__ __align__(16) float g_Wc[2 * 4096];

// ---------------- packed fp32x2 helpers (SASS FFMA2, PTX-only) ----------------
__device__ __forceinline__ unsigned long long ffma2(unsigned long long a,
                                                    unsigned long long b,
                                                    unsigned long long c) {
    unsigned long long d;
    asm("fma.rn.f32x2 %0, %1, %2, %3;" : "=l"(d) : "l"(a), "l"(b), "l"(c));
    return d;
}
__device__ __forceinline__ float redu2(unsigned long long v) {
    float lo, hi;
    asm("mov.b64 {%0, %1}, %2;" : "=f"(lo), "=f"(hi) : "l"(v));
    return lo + hi;
}
// expand 2 fp16 -> packed fp32x2 u64
__device__ __forceinline__ unsigned long long h2pack(unsigned int u) {
    __half2 h = *reinterpret_cast<const __half2*>(&u);
    float2 f = __half22float2(h);
    unsigned long long r;
    asm("mov.b64 %0, {%1, %2};" : "=l"(r) : "f"(f.x), "f"(f.y));
    return r;
}
__device__ __forceinline__ float sigm(float x) {
    return __fdividef(1.0f, 1.0f + __expf(-x));
}
__device__ __forceinline__ float fast_tanh(float x) {
    float ax = fabsf(x);
    float e = __expf(ax + ax);
    float t = 1.0f - __fdividef(2.0f, e + 1.0f);
    return copysignf(t, x);
}
// reduce packed acc + combine the two k-halves (lanes l, l^16)
__device__ __forceinline__ float redsum(unsigned long long v) {
    float r = redu2(v);
    r += __shfl_xor_sync(0xffffffffu, r, 16);
    return r;
}

// ---------------- weight layout prep ----------------
__global__ void __launch_bounds__(256) prep_weights(
    const float* __restrict__ Win0, const float* __restrict__ Wg0,
    const float* __restrict__ Wrec0, const float* __restrict__ Win1,
    const float* __restrict__ Wrec1, const float* __restrict__ Wg1) {
    int idx = blockIdx.x * 256 + threadIdx.x;
    if (idx < 16384) {  // 64-k mats: Win0 seq / Wg0 seq
        int m = idx >> 13;
        int a = idx & 8191;
        int e = a & 7, t = a >> 3;
        int j = t & 127, t2 = t >> 7;
        int hf = t2 & 1, i = t2 >> 1;
        int k = hf * 32 + i * 8 + e;
        float v = m ? Wg0[j * 224 + k] : Win0[j * 96 + k];
        g_Wh[idx] = __float2half_rn(v);
    } else if (idx < WH_TOTAL) {  // 128-k mats
        int m = (idx - 16384) >> 14;
        int a = (idx - 16384) & 16383;
        int e = a & 7, t = a >> 3;
        int j = t & 127, t2 = t >> 7;
        int hf = t2 & 1, i = t2 >> 1;
        int k = hf * 64 + i * 8 + e;
        float v;
        switch (m) {
            case 0: v = Wg0[j * 224 + 96 + k]; break;
            case 1: v = Wrec0[j * 128 + k]; break;
            case 2: v = Win1[j * 128 + k]; break;
            case 3: v = Wg1[j * 256 + k]; break;
            case 4: v = Wg1[j * 256 + 128 + k]; break;
            default: v = Wrec1[j * 128 + k]; break;
        }
        g_Wh[idx] = __float2half_rn(v);
    } else if (idx < WH_TOTAL + 8192) {  // ctx parts, fp32 k-quad
        int r = idx - WH_TOTAL;
        int m = r >> 12;
        int a = r & 4095;
        int j = (a >> 2) & 127;
        int k = ((a >> 9) << 2) | (a & 3);
        g_Wc[r] = m ? Wg0[j * 224 + 64 + k] : Win0[j * 96 + 64 + k];
    }
}

// Half-split dual mat-vec, fp16 weights. Thread covers row jl, k-half `half`
// (folded into W pointers and x offset). ITERS = (k/2)/8. x smem slot layout:
// slot = i*16 + half*8 + e. Halves combined via one shfl.
template <int ITERS, int XS>
__device__ __forceinline__ void dualmv_h(const __half* __restrict__ Wa,
                                         const __half* __restrict__ Wb,
                                         const float* __restrict__ x,
                                         float ra[4], float rb[4]) {
    unsigned long long a[4] = {0, 0, 0, 0};
    unsigned long long c[4] = {0, 0, 0, 0};
#pragma unroll
    for (int i = 0; i < ITERS; ++i) {
        uint4 wra = __ldg(reinterpret_cast<const uint4*>(Wa + (size_t)i * 2048));
        uint4 wrb = __ldg(reinterpret_cast<const uint4*>(Wb + (size_t)i * 2048));
        unsigned long long wa0 = h2pack(wra.x), wa1 = h2pack(wra.y);
        unsigned long long wa2 = h2pack(wra.z), wa3 = h2pack(wra.w);
        unsigned long long wb0 = h2pack(wrb.x), wb1 = h2pack(wrb.y);
        unsigned long long wb2 = h2pack(wrb.z), wb3 = h2pack(wrb.w);
#pragma unroll
        for (int b = 0; b < 4; ++b) {
            ulonglong2 x0 = *reinterpret_cast<const ulonglong2*>(x + b * XS + i * 16);
            ulonglong2 x1 = *reinterpret_cast<const ulonglong2*>(x + b * XS + i * 16 + 4);
            a[b] = ffma2(wa0, x0.x, a[b]);
            a[b] = ffma2(wa1, x0.y, a[b]);
            a[b] = ffma2(wa2, x1.x, a[b]);
            a[b] = ffma2(wa3, x1.y, a[b]);
            c[b] = ffma2(wb0, x0.x, c[b]);
            c[b] = ffma2(wb1, x0.y, c[b]);
            c[b] = ffma2(wb2, x1.x, c[b]);
            c[b] = ffma2(wb3, x1.y, c[b]);
        }
    }
#pragma unroll
    for (int b = 0; b < 4; ++b) {
        ra[b] = redsum(a[b]);
        rb[b] = redsum(c[b]);
    }
}

// RK4 for one cell; cu/nx ping-pong h buffers (1 bar per sub-phase). Only
// half==0 threads store. Last sub-phase stores h0r when WRITE_H0 (cell-0 state
// staged for the next step) instead of the new h.
template <bool WRITE_H0>
__device__ __forceinline__ void rk4_cell(const __half* __restrict__ Wg,
                                         const __half* __restrict__ Wr, float itau,
                                         const float* xin, const float* xg, float* hb,
                                         const float* h0r, float*& cu, float*& nx,
                                         int xoff, int hslot, int half) {
    float ka[4] = {0.f, 0.f, 0.f, 0.f};
    float ht[4] = {hb[0], hb[1], hb[2], hb[3]};
#pragma unroll
    for (int sub = 0; sub < 4; ++sub) {
        float ra[4], rb[4];
        dualmv_h<8, HSTRIDE>(Wg, Wr, cu + xoff, ra, rb);
        const float kw = (sub == 0 || sub == 3) ? 1.0f : 2.0f;
        const float cv = (sub < 2) ? 0.5f : 1.0f;
#pragma unroll
        for (int b = 0; b < 4; ++b) {
            float gate = sigm(fast_tanh(ra[b] + xg[b]));
            float kv = fmaf(gate, rb[b], fmaf(-ht[b], itau, xin[b]));
            ka[b] = fmaf(kw, kv, ka[b]);
            float nh = (sub < 3) ? fmaf(cv, kv, hb[b])
                                 : fast_tanh(fmaf(ka[b], 0.16666667f, hb[b]));
            ht[b] = nh;
            if (half == 0)
                nx[b * HSTRIDE + hslot] = (sub == 3 && WRITE_H0) ? h0r[b] : nh;
        }
        __syncthreads();
        float* t = cu; cu = nx; nx = t;
    }
    hb[0] = ht[0]; hb[1] = ht[1]; hb[2] = ht[2]; hb[3] = ht[3];
}

// ---------------- persistent recurrence: 128 CTAs x 256 threads ----------------
// Warp w covers rows jl = w*16 + (lane&15); lane half = lane>>4 covers one k-half.
__global__ void __launch_bounds__(256, 1)
ltc_recurrent(const float* __restrict__ seq, const float* __restrict__ ctx,
              const float* __restrict__ tau0, const float* __restrict__ bg0,
              const float* __restrict__ tau1, const float* __restrict__ bg1,
              const float* __restrict__ W1, const float* __restrict__ b1,
              const float* __restrict__ W2, const float* __restrict__ b2,
              float* __restrict__ out) {
    __shared__ __align__(16) float hhA[4 * HSTRIDE];
    __shared__ __align__(16) float hhB[4 * HSTRIDE];
    __shared__ __align__(16) float xs[4 * XSTRIDE];
    __shared__ __align__(16) float xc[4 * 32];
    __shared__ __align__(16) float st0[512];
    __shared__ __align__(16) float st1[512];
    const int tid = threadIdx.x;
    const int lane = tid & 31;
    const int w = tid >> 5;
    const int half = lane >> 4;
    const int jl = (w << 4) + (lane & 15);
    const int xoff = half * 8;
    // smem slot of h[jl]: slot = i*16 + half_j*8 + e for jl = half_j*64+i*8+e
    const int hslot = (((jl >> 3) & 7) << 4) + ((jl >> 6) << 3) + (jl & 7);
    const int b0g = blockIdx.x * 4;

    const float it0 = __fdividef(1.0f, log1pf(__expf(tau0[jl])) + 1.0f);
    const float it1 = __fdividef(1.0f, log1pf(__expf(tau1[jl])) + 1.0f);
    const float bg1j = bg1[jl];

    const int wo = (half * 128 + jl) * 8;
    const __half* Win0s = g_Wh + OFF_WIN0S + wo;
    const __half* Wg0s  = g_Wh + OFF_WG0S  + wo;
    const __half* Wg0h  = g_Wh + OFF_WG0H  + wo;
    const __half* Wrec0 = g_Wh + OFF_WREC0 + wo;
    const __half* Win1  = g_Wh + OFF_WIN1  + wo;
    const __half* Wg1x  = g_Wh + OFF_WG1X  + wo;
    const __half* Wg1h  = g_Wh + OFF_WG1H  + wo;
    const __half* Wrec1 = g_Wh + OFF_WREC1 + wo;

    // ---- step-invariant ctx projection (threads 0-127, fp32 k-quad) ----
    if (tid < 128) {
        int b = tid >> 5, i = tid & 31;
        xc[b * 32 + i] = ctx[(size_t)(b0g + b) * 32 + i];
    }
    __syncthreads();
    if (tid < 128) {
        const int j = tid;
        const float* Wa = g_Wc + j * 4;
        const float* Wb = g_Wc + 4096 + j * 4;
        unsigned long long a[4] = {0, 0, 0, 0}, c[4] = {0, 0, 0, 0};
#pragma unroll
        for (int kq = 0; kq < 8; ++kq) {
            ulonglong2 wa = __ldg(reinterpret_cast<const ulonglong2*>(Wa + kq * 512));
            ulonglong2 wb = __ldg(reinterpret_cast<const ulonglong2*>(Wb + kq * 512));
#pragma unroll
            for (int b = 0; b < 4; ++b) {
                ulonglong2 xv = *reinterpret_cast<const ulonglong2*>(xc + b * 32 + kq * 4);
                a[b] = ffma2(wa.x, xv.x, a[b]);
                a[b] = ffma2(wa.y, xv.y, a[b]);
                c[b] = ffma2(wb.x, xv.x, c[b]);
                c[b] = ffma2(wb.y, xv.y, c[b]);
            }
        }
        const float bg0j = bg0[j];
#pragma unroll
        for (int b = 0; b < 4; ++b) {
            st0[b * 128 + j] = redu2(a[b]);
            st1[b * 128 + j] = redu2(c[b]) + bg0j;
        }
    }
    __syncthreads();
    float xinc[4], xgc[4];
#pragma unroll
    for (int b = 0; b < 4; ++b) {
        xinc[b] = st0[b * 128 + jl];
        xgc[b] = st1[b * 128 + jl];
    }

    float h0r[4] = {0.f, 0.f, 0.f, 0.f}, h1r[4] = {0.f, 0.f, 0.f, 0.f};
    float* cu = hhA;
    float* nx = hhB;
    hhA[tid] = 0.f;
    hhA[256 + tid] = 0.f;

    for (int s = 0; s < S_LEN; ++s) {
        // load this step's seq slice into xs (slot = i*16 + half*8 + e, k<64)
        {
            int b = tid >> 6, k = tid & 63;
            float v = seq[((size_t)(b0g + b) * S_LEN + s) * 64 + k];
            int sl = (((k >> 3) & 3) << 4) + ((k >> 5) << 3) + (k & 7);
            xs[b * XSTRIDE + sl] = v;
        }
        __syncthreads();

        // cell-0 input projections (seq part) + ctx base
        float xin0[4], xg0[4];
        dualmv_h<4, XSTRIDE>(Win0s, Wg0s, xs + xoff, xin0, xg0);
#pragma unroll
        for (int b = 0; b < 4; ++b) { xin0[b] += xinc[b]; xg0[b] += xgc[b]; }

        // cell 0 (cu holds h0; leaves h0_new in cu and h0r)
        rk4_cell<false>(Wg0h, Wrec0, it0, xin0, xg0, h0r, nullptr, cu, nx, xoff,
                        hslot, half);

        // cell-1 input projections from h0_new; stage h1 into nx
        float xin1[4], xg1[4];
        dualmv_h<8, HSTRIDE>(Win1, Wg1x, cu + xoff, xin1, xg1);
#pragma unroll
        for (int b = 0; b < 4; ++b) {
            xg1[b] += bg1j;
            if (half == 0) nx[b * HSTRIDE + hslot] = h1r[b];
        }
        __syncthreads();
        { float* t = cu; cu = nx; nx = t; }

        // cell 1 (last sub writes h0_new back for the next step's cell 0)
        rk4_cell<true>(Wg1h, Wrec1, it1, xin1, xg1, h1r, h0r, cu, nx, xoff,
                       hslot, half);
    }

    // ---- classifier: sigmoid(relu(h1 @ W1^T + b1) @ W2^T + b2) ----
    __syncthreads();
    if (half == 0) {
#pragma unroll
        for (int b = 0; b < 4; ++b) st0[b * 128 + jl] = h1r[b];
    }
    __syncthreads();
    if (tid < 128) {
        const int b = tid >> 5, ln = tid & 31;
        float a0 = b1[ln], a1 = b1[ln + 32];
        const float* hv = st0 + b * 128;
        const float* w0 = W1 + ln * 128;
        const float* w1 = W1 + (ln + 32) * 128;
#pragma unroll 8
        for (int k = 0; k < 128; ++k) {
            float h = hv[k];
            a0 = fmaf(h, w0[k], a0);
            a1 = fmaf(h, w1[k], a1);
        }
        a0 = fmaxf(a0, 0.f);
        a1 = fmaxf(a1, 0.f);
        float p = a0 * __ldg(W2 + ln) + a1 * __ldg(W2 + ln + 32);
#pragma unroll
        for (int off = 16; off; off >>= 1) p += __shfl_xor_sync(0xffffffffu, p, off);
        if (ln == 0) out[b0g + b] = sigm(p + b2[0]);
    }
}

extern "C" void kernel_launch(void* const* d_in, const int* in_sizes, int n_in,
                              void* d_out, int out_size) {
    const float* seq   = (const float*)d_in[0];
    const float* ctx   = (const float*)d_in[1];
    const float* tau0  = (const float*)d_in[2];
    const float* Win0  = (const float*)d_in[3];
    const float* Wrec0 = (const float*)d_in[4];
    const float* Wg0   = (const float*)d_in[5];
    const float* bg0   = (const float*)d_in[6];
    const float* tau1  = (const float*)d_in[7];
    const float* Win1  = (const float*)d_in[8];
    const float* Wrec1 = (const float*)d_in[9];
    const float* Wg1   = (const float*)d_in[10];
    const float* bg1   = (const float*)d_in[11];
    const float* W1    = (const float*)d_in[12];
    const float* b1    = (const float*)d_in[13];
    const float* W2    = (const float*)d_in[14];
    const float* b2    = (const float*)d_in[15];
    float* out = (float*)d_out;

    prep_weights<<<(WH_TOTAL + 8192 + 255) / 256, 256>>>(Win0, Wg0, Wrec0, Win1,
                                                         Wrec1, Wg1);
    ltc_recurrent<<<128, 256>>>(seq, ctx, tau0, bg0, tau1, bg1, W1, b1, W2, b2, out);
}